// round 16
// baseline (speedup 1.0000x reference)
#include <cuda_runtime.h>
#include <cuda_fp16.h>

#define NROW 1024
#define HDIM 300
#define MID  100
#define NJ   1025
#define OUT_LD 1025
#define MPAD 104
#define S2P  1088
#define KSPLIT 5
#define HC 60            // h per split chunk (5*60 = 300)
#define PPITCH 112       // partial pitch in floats
#define S2HP 72          // s2 chunk pitch in halves (64 + 8 pad)
#define NBLK23 128

// ---- device scratch (zero-initialized at load; pads never written -> stay 0) ----
__device__ __align__(16) float g_part[KSPLIT * 2048 * PPITCH];  // raw GEMM partials
__device__ __align__(16) float g_s1[NROW * MPAD];
__device__ __align__(16) float g_s2T[MID * S2P];
__device__ __align__(16) float g_w2[MID];          // 0.5*w2
__device__ float g_C[1];
__device__ float g_blockloss[NBLK23];
__device__ unsigned g_done;

__device__ __forceinline__ __half2 tanh_h2(__half2 x) {
    unsigned r, xi = *reinterpret_cast<unsigned*>(&x);
    asm("tanh.approx.f16x2 %0, %1;" : "=r"(r) : "r"(xi));
    return *reinterpret_cast<__half2*>(&r);
}

// ================= k1: split-K dual GEMM =================
// grid (128, 5): blockIdx.x = row-block (16 virtual rows), blockIdx.y = h-chunk.
__global__ void __launch_bounds__(256) k1_gemm(const float* __restrict__ sent,
                                               const float* __restrict__ W1) {
    __shared__ float4 rsI[15][17];      // [h4][row]
    __shared__ float4 wsI[15][113];     // [h4][m]

    int b  = blockIdx.x;
    int kc = blockIdx.y;
    int tid = threadIdx.x;

    bool isS1 = (b < 64);
    int r0 = (b & 63) * 16;
    int woff = (isS1 ? 0 : HDIM) + kc * HC;
    const float* src = sent + (size_t)r0 * HDIM + kc * HC;

    if (tid < 240) {
        int rr = tid / 15, h4 = tid % 15;
        rsI[h4][rr] = *(const float4*)(src + rr * HDIM + h4 * 4);
    }
    for (int q = tid; q < 112 * 15; q += 256) {
        int m = q / 15, h4 = q % 15;
        float4 v = make_float4(0.f, 0.f, 0.f, 0.f);
        if (m < MID) v = *(const float4*)(W1 + m * (2 * HDIM) + woff + h4 * 4);
        wsI[h4][m] = v;
    }
    __syncthreads();

    int r  = tid & 15;
    int mg = tid >> 4;

    float acc[7];
#pragma unroll
    for (int c = 0; c < 7; c++) acc[c] = 0.f;

#pragma unroll
    for (int h4 = 0; h4 < 15; h4++) {
        float4 ra = rsI[h4][r];
#pragma unroll
        for (int c = 0; c < 7; c++) {
            float4 wv = wsI[h4][mg + 16 * c];
            acc[c] = fmaf(ra.x, wv.x, acc[c]);
            acc[c] = fmaf(ra.y, wv.y, acc[c]);
            acc[c] = fmaf(ra.z, wv.z, acc[c]);
            acc[c] = fmaf(ra.w, wv.w, acc[c]);
        }
    }

    int vr = b * 16 + r;
    float* dst = g_part + ((size_t)kc * 2048 + vr) * PPITCH;
#pragma unroll
    for (int c = 0; c < 7; c++) {
        int m = mg + 16 * c;
        if (m < MID) dst[m] = acc[c];
    }
}

// ================= k1b: reduce split-K partials + prep =================
__global__ void __launch_bounds__(256) k1b_reduce(const float* __restrict__ b1,
                                                  const float* __restrict__ W2,
                                                  const float* __restrict__ b2) {
    int tid = threadIdx.x;
    if (blockIdx.x == 800) {   // prep
        if (tid < MID) {
            g_w2[tid] = 0.5f * W2[tid];
            g_s2T[tid * S2P + 0] = 0.5f * b1[tid];   // j=0: pm row is zeros
        }
        if (tid == 0) {
            float s = 0.f;
#pragma unroll
            for (int m = 0; m < MID; m++) s += W2[m];
            g_C[0] = b2[0] + 0.5f * s;
        }
        return;
    }
    int gid = blockIdx.x * 256 + tid;
    int vr = gid / MID;
    int m  = gid - vr * MID;
    float s = 0.f;
#pragma unroll
    for (int k = 0; k < KSPLIT; k++)
        s += g_part[((size_t)k * 2048 + vr) * PPITCH + m];
    if (vr < NROW) {
        g_s1[vr * MPAD + m] = 0.5f * s;
    } else {
        int j = vr - 1023;   // 1..1024
        g_s2T[m * S2P + j] = 0.5f * (s + b1[m]);
    }
}

// ================= k23: fused scores + softmax + loss =================
// grid 128 x 512: block = 8 rows. Warp wid: row = wid&7, half = wid>>3.
// Round t stages chunks 2t (buf A) and 2t+1 (buf B); half 0 computes A, half 1 B.
// Lane covers j = c*64 + 2*lane, +1. e-values stay in registers; final softmax
// written straight to out (SCALAR stores: out+1 breaks 8B alignment).
__global__ void __launch_bounds__(512) k23_fused(const int* __restrict__ tgt,
                                                 float* __restrict__ out) {
    __shared__ float s1s[8][MPAD];
    __shared__ __align__(16) __half s2A[MID * S2HP];
    __shared__ __align__(16) __half s2B[MID * S2HP];
    __shared__ float w2s[MID];
    __shared__ float csh;
    __shared__ float rowsum[8][2];
    __shared__ float lred[16];
    __shared__ bool amLast;

    int tid  = threadIdx.x;
    int wid  = tid >> 5;
    int lane = tid & 31;
    int row  = wid & 7;
    int half = wid >> 3;
    int i0   = blockIdx.x * 8;
    int i    = i0 + row;

    for (int q = tid; q < 8 * MPAD; q += 512)
        s1s[q / MPAD][q % MPAD] = g_s1[(size_t)(i0 + q / MPAD) * MPAD + (q % MPAD)];
    if (tid < MID) w2s[tid] = g_w2[tid];
    if (tid == 0) csh = g_C[0];
    int tgv = tgt[i];

    float e[18];
    float lossacc = 0.f;
    float sumE = 0.f;

#pragma unroll 1
    for (int t = 0; t < 9; t++) {
        int cA = 2 * t, cB = 2 * t + 1;
        __syncthreads();   // previous round's readers done
        for (int q = tid; q < MID * 16; q += 512) {
            int m = q >> 4, f4 = q & 15;
            float4 v = *(const float4*)(g_s2T + m * S2P + cA * 64 + f4 * 4);
            *(__half2*)(s2A + m * S2HP + f4 * 4)     = __floats2half2_rn(v.x, v.y);
            *(__half2*)(s2A + m * S2HP + f4 * 4 + 2) = __floats2half2_rn(v.z, v.w);
        }
        if (cB < 17) {
            for (int q = tid; q < MID * 16; q += 512) {
                int m = q >> 4, f4 = q & 15;
                float4 v = *(const float4*)(g_s2T + m * S2P + cB * 64 + f4 * 4);
                *(__half2*)(s2B + m * S2HP + f4 * 4)     = __floats2half2_rn(v.x, v.y);
                *(__half2*)(s2B + m * S2HP + f4 * 4 + 2) = __floats2half2_rn(v.z, v.w);
            }
        }
        __syncthreads();

        int c = 2 * t + half;
        float a0 = 0.f, a1 = 0.f;
        if (c < 17) {
            const __half* buf = half ? s2B : s2A;
#pragma unroll 4
            for (int m = 0; m < MID; m++) {
                __half2 ah = __float2half2_rn(s1s[row][m]);
                float w = w2s[m];
                __half2 p = *(const __half2*)(buf + m * S2HP + lane * 2);
                __half2 tv = tanh_h2(__hadd2(ah, p));
                a0 = fmaf(w, __low2float(tv),  a0);
                a1 = fmaf(w, __high2float(tv), a1);
            }
        }
        float s0 = a0 + csh;
        float s1v = a1 + csh;
        float e0 = __expf(s0);
        float e1 = __expf(s1v);
        int j0 = c * 64 + 2 * lane;
        bool v0 = (c < 17) && (j0 < NJ);
        bool v1 = (c < 17) && (j0 + 1 < NJ);
        if (v0) { sumE += e0; lossacc += fabsf(s0  - ((j0     == tgv) ? 1.f : 0.f)); }
        if (v1) { sumE += e1; lossacc += fabsf(s1v - ((j0 + 1 == tgv) ? 1.f : 0.f)); }
        e[2 * t]     = v0 ? e0 : 0.f;
        e[2 * t + 1] = v1 ? e1 : 0.f;
    }

    // row-half reductions
#pragma unroll
    for (int off = 16; off > 0; off >>= 1) {
        sumE    += __shfl_xor_sync(0xffffffffu, sumE, off);
        lossacc += __shfl_xor_sync(0xffffffffu, lossacc, off);
    }
    if (lane == 0) { rowsum[row][half] = sumE; lred[wid] = lossacc; }
    __syncthreads();

    float inv = 1.0f / (rowsum[row][0] + rowsum[row][1]);
    float* orow = out + 1 + (size_t)i * OUT_LD;
#pragma unroll
    for (int t = 0; t < 9; t++) {
        int c = 2 * t + half;
        int j0 = c * 64 + 2 * lane;
        if (c < 17) {
            if (j0 < NJ)     orow[j0]     = e[2 * t] * inv;
            if (j0 + 1 < NJ) orow[j0 + 1] = e[2 * t + 1] * inv;
        }
    }

    // block loss partial -> global; last block finalizes
    if (tid < 16) {
        float s = lred[tid];
#pragma unroll
        for (int off = 8; off > 0; off >>= 1)
            s += __shfl_xor_sync(0xffffu, s, off);
        if (tid == 0) g_blockloss[blockIdx.x] = s;
    }
    if (tid == 0) {
        __threadfence();
        amLast = (atomicAdd(&g_done, 1u) == NBLK23 - 1);
    }
    __syncthreads();
    if (amLast) {
        if (tid < 128) {
            float s = g_blockloss[tid];
#pragma unroll
            for (int off = 16; off > 0; off >>= 1)
                s += __shfl_xor_sync(0xffffffffu, s, off);
            if ((tid & 31) == 0) lred[tid >> 5] = s;
        }
        __syncthreads();
        if (tid == 0) {
            float tl = lred[0] + lred[1] + lred[2] + lred[3];
            out[0] = tl * (1.0f / (1024.0f * 1025.0f));
            g_done = 0;   // replay-safe reset
        }
    }
}

extern "C" void kernel_launch(void* const* d_in, const int* in_sizes, int n_in,
                              void* d_out, int out_size) {
    const float* sentence;
    const int*   tgt;
    const float* W1;
    const float* b1;
    const float* W2;
    const float* b2;

    if (n_in >= 6 && in_sizes[1] == 1024) {
        sentence = (const float*)d_in[0];
        tgt      = (const int*)d_in[1];
        W1       = (const float*)d_in[2];
        b1       = (const float*)d_in[3];
        W2       = (const float*)d_in[4];
        b2       = (const float*)d_in[5];
    } else {
        sentence = (const float*)d_in[0];
        W1       = (const float*)d_in[1];
        b1       = (const float*)d_in[2];
        W2       = (const float*)d_in[3];
        b2       = (const float*)d_in[4];
        tgt      = (const int*)d_in[5];
    }

    float* out = (float*)d_out;

    dim3 g1(128, KSPLIT);
    k1_gemm<<<g1, 256>>>(sentence, W1);
    k1b_reduce<<<801, 256>>>(b1, W2, b2);
    k23_fused<<<NBLK23, 512>>>(tgt, out);
}

// round 17
// speedup vs baseline: 1.2981x; 1.2981x over previous
#include <cuda_runtime.h>
#include <cuda_fp16.h>

#define NROW 1024
#define HDIM 300
#define MID  100
#define NJ   1025
#define OUT_LD 1025
#define MPAD 104
#define S2P  1088
#define SCP  1088
#define NTILE 544        // 17 j-tiles x 32 i-tiles
#define S2HP 72          // k2 s2 tile pitch in halves (64 + 8 pad)
#define KSPLIT 5
#define HC 60            // h per split chunk (5*60 = 300)
#define PPITCH 112       // partial pitch in floats
#define NBLK3 256        // k3 blocks (4 rows each)

// ---- device scratch (zero-initialized at load; pads never written -> stay 0) ----
__device__ __align__(16) float g_part[KSPLIT * 2048 * PPITCH];  // raw GEMM partials
__device__ __align__(16) float g_s1[NROW * MPAD];
__device__ __align__(16) float g_s2T[MID * S2P];
__device__ __align__(16) float g_w2[MID];            // 0.5*w2
__device__ __align__(16) float g_scores[NROW * SCP]; // exp(score) scratch
__device__ float g_C[1];
__device__ float g_blockloss[NTILE];
__device__ unsigned g_done;

__device__ __forceinline__ __half2 tanh_h2(__half2 x) {
    unsigned r, xi = *reinterpret_cast<unsigned*>(&x);
    asm("tanh.approx.f16x2 %0, %1;" : "=r"(r) : "r"(xi));
    return *reinterpret_cast<__half2*>(&r);
}

// ================= k1: split-K dual GEMM =================
// grid (128, 5): blockIdx.x = row-block (16 virtual rows), blockIdx.y = h-chunk.
// rs: [h4][row] (inner ra conflict-free). ws: m-major [m][h4] (staging STS
// contiguous; inner wv is a 2-address warp broadcast).
__global__ void __launch_bounds__(256) k1_gemm(const float* __restrict__ sent,
                                               const float* __restrict__ W1) {
    __shared__ float4 rsI[15][17];      // [h4][row]
    __shared__ float4 wsM[112][16];     // [m][h4] (15 used)

    int b  = blockIdx.x;
    int kc = blockIdx.y;
    int tid = threadIdx.x;

    bool isS1 = (b < 64);
    int r0 = (b & 63) * 16;
    int woff = (isS1 ? 0 : HDIM) + kc * HC;
    const float* src = sent + (size_t)r0 * HDIM + kc * HC;

    if (tid < 240) {
        int rr = tid / 15, h4 = tid % 15;
        rsI[h4][rr] = *(const float4*)(src + rr * HDIM + h4 * 4);
    }
    for (int q = tid; q < 112 * 15; q += 256) {
        int m = q / 15, h4 = q % 15;
        float4 v = make_float4(0.f, 0.f, 0.f, 0.f);
        if (m < MID) v = *(const float4*)(W1 + m * (2 * HDIM) + woff + h4 * 4);
        wsM[m][h4] = v;
    }
    __syncthreads();

    int r  = tid & 15;
    int mg = tid >> 4;

    float acc[7];
#pragma unroll
    for (int c = 0; c < 7; c++) acc[c] = 0.f;

#pragma unroll
    for (int h4 = 0; h4 < 15; h4++) {
        float4 ra = rsI[h4][r];
#pragma unroll
        for (int c = 0; c < 7; c++) {
            float4 wv = wsM[mg + 16 * c][h4];
            acc[c] = fmaf(ra.x, wv.x, acc[c]);
            acc[c] = fmaf(ra.y, wv.y, acc[c]);
            acc[c] = fmaf(ra.z, wv.z, acc[c]);
            acc[c] = fmaf(ra.w, wv.w, acc[c]);
        }
    }

    int vr = b * 16 + r;
    float* dst = g_part + ((size_t)kc * 2048 + vr) * PPITCH;
#pragma unroll
    for (int c = 0; c < 7; c++) {
        int m = mg + 16 * c;
        if (m < MID) dst[m] = acc[c];
    }
}

// ================= k1b: reduce split-K partials (4 outputs/thread) + prep =================
__global__ void __launch_bounds__(256) k1b_reduce(const float* __restrict__ b1,
                                                  const float* __restrict__ W2,
                                                  const float* __restrict__ b2) {
    int tid = threadIdx.x;
    if (blockIdx.x == 200) {   // prep
        if (tid < MID) {
            g_w2[tid] = 0.5f * W2[tid];
            g_s2T[tid * S2P + 0] = 0.5f * b1[tid];   // j=0: pm row is zeros
        }
        if (tid == 0) {
            float s = 0.f;
#pragma unroll
            for (int m = 0; m < MID; m++) s += W2[m];
            g_C[0] = b2[0] + 0.5f * s;
        }
        return;
    }
    int base = blockIdx.x * 256 + tid;   // 0..51199
    float s[4];
#pragma unroll
    for (int u = 0; u < 4; u++) s[u] = 0.f;
#pragma unroll
    for (int k = 0; k < KSPLIT; k++) {
#pragma unroll
        for (int u = 0; u < 4; u++) {
            int gid = base + 51200 * u;
            int vr = gid / MID;
            int m  = gid - vr * MID;
            s[u] += g_part[((size_t)k * 2048 + vr) * PPITCH + m];
        }
    }
#pragma unroll
    for (int u = 0; u < 4; u++) {
        int gid = base + 51200 * u;
        int vr = gid / MID;
        int m  = gid - vr * MID;
        if (vr < NROW) {
            g_s1[vr * MPAD + m] = 0.5f * s[u];
        } else {
            int j = vr - 1023;   // 1..1024
            g_s2T[m * S2P + j] = 0.5f * (s[u] + b1[m]);
        }
    }
}

// ================= k2: pairwise scores (f16 add + f16x2 tanh, f32 accumulate) =================
// Tile 32i x 64j, 256 threads: thread = 1 i x 8 j. exp(score) -> g_scores + loss partial.
__global__ void __launch_bounds__(256) k2_scores(const int* __restrict__ tgt) {
    __shared__ float  s1t[32][MPAD];
    __shared__ __align__(16) __half s2h[MID * S2HP];   // [m][j] as f16
    __shared__ float  w2t[MID];
    __shared__ float  csh;
    __shared__ float  red[8];

    int tid = threadIdx.x;
    int i0 = blockIdx.y * 32;
    int j0 = blockIdx.x * 64;

    for (int q = tid; q < 32 * MPAD; q += 256)
        s1t[q / MPAD][q % MPAD] = g_s1[(i0 + q / MPAD) * MPAD + (q % MPAD)];
    for (int q = tid; q < MID * 16; q += 256) {
        int m = q >> 4, f4 = q & 15;
        float4 v = *(const float4*)(g_s2T + m * S2P + j0 + f4 * 4);
        *(__half2*)(s2h + m * S2HP + f4 * 4)     = __floats2half2_rn(v.x, v.y);
        *(__half2*)(s2h + m * S2HP + f4 * 4 + 2) = __floats2half2_rn(v.z, v.w);
    }
    if (tid < MID) w2t[tid] = g_w2[tid];
    if (tid == 0) csh = g_C[0];
    __syncthreads();

    int ti = tid >> 3;
    int tg = tid & 7;
    float acc[8];
#pragma unroll
    for (int c = 0; c < 8; c++) acc[c] = 0.f;

#pragma unroll 2
    for (int m = 0; m < MID; m++) {
        __half2 ah = __float2half2_rn(s1t[ti][m]);
        float w = w2t[m];
        uint4 pv = *(const uint4*)(s2h + m * S2HP + tg * 8);  // 8 halves
#pragma unroll
        for (int c = 0; c < 4; c++) {
            unsigned pu = (c == 0) ? pv.x : (c == 1) ? pv.y : (c == 2) ? pv.z : pv.w;
            __half2 p = *reinterpret_cast<__half2*>(&pu);
            __half2 t = tanh_h2(__hadd2(ah, p));
            acc[2 * c]     = fmaf(w, __low2float(t),  acc[2 * c]);
            acc[2 * c + 1] = fmaf(w, __high2float(t), acc[2 * c + 1]);
        }
    }

    float C = csh;
    int i = i0 + ti;
    int jbase = j0 + tg * 8;
    int tgv = tgt[i];
    float lossacc = 0.f;
    float e[8];
#pragma unroll
    for (int c = 0; c < 8; c++) {
        int j = jbase + c;
        float s = acc[c] + C;
        e[c] = __expf(s);
        if (j < NJ) lossacc += fabsf(s - ((j == tgv) ? 1.f : 0.f));
    }
    float* dst = g_scores + (size_t)i * SCP + jbase;
    *(float4*)dst       = make_float4(e[0], e[1], e[2], e[3]);
    *(float4*)(dst + 4) = make_float4(e[4], e[5], e[6], e[7]);

    // deterministic block loss reduce
#pragma unroll
    for (int off = 16; off > 0; off >>= 1)
        lossacc += __shfl_xor_sync(0xffffffffu, lossacc, off);
    if ((tid & 31) == 0) red[tid >> 5] = lossacc;
    __syncthreads();
    if (tid == 0) {
        float s = red[0];
#pragma unroll
        for (int w = 1; w < 8; w++) s += red[w];
        g_blockloss[blockIdx.y * 17 + blockIdx.x] = s;
    }
}

// ================= k3: 4 rows/block: row-sum + normalize; last block: loss =================
__global__ void __launch_bounds__(256) k3_softmax(float* __restrict__ out) {
    __shared__ float rowsum[4][2];
    __shared__ float lred[8];
    __shared__ bool amLast;
    int t = threadIdx.x;
    int sub = t >> 6;          // row within block (0..3)
    int q   = t & 63;          // 64 threads per row
    int i = blockIdx.x * 4 + sub;
    const float* row = g_scores + (size_t)i * SCP;

    float4 v[4];
#pragma unroll
    for (int k = 0; k < 4; k++)
        v[k] = ((const float4*)row)[q + 64 * k];   // covers j 0..1023
    float extra = row[1024];
    float sum = 0.f;
#pragma unroll
    for (int k = 0; k < 4; k++)
        sum += (v[k].x + v[k].y) + (v[k].z + v[k].w);
    if (q == 0) sum += extra;

#pragma unroll
    for (int off = 16; off > 0; off >>= 1)
        sum += __shfl_xor_sync(0xffffffffu, sum, off);
    if ((t & 31) == 0) rowsum[sub][(q >> 5) & 1] = sum;
    __syncthreads();
    float inv = 1.0f / (rowsum[sub][0] + rowsum[sub][1]);

    float* orow = out + 1 + (size_t)i * OUT_LD;
#pragma unroll
    for (int k = 0; k < 4; k++) {
        int j = (q + 64 * k) * 4;
        orow[j]     = v[k].x * inv;
        orow[j + 1] = v[k].y * inv;
        orow[j + 2] = v[k].z * inv;
        orow[j + 3] = v[k].w * inv;
    }
    if (q == 0) orow[1024] = extra * inv;

    // ticket: last block reduces k2's loss partials (fixed order, replay-safe)
    if (t == 0) {
        __threadfence();
        amLast = (atomicAdd(&g_done, 1u) == NBLK3 - 1);
    }
    __syncthreads();
    if (amLast) {
        float s = g_blockloss[t] + g_blockloss[t + 256];
        if (t < NTILE - 512) s += g_blockloss[t + 512];
#pragma unroll
        for (int off = 16; off > 0; off >>= 1)
            s += __shfl_xor_sync(0xffffffffu, s, off);
        if ((t & 31) == 0) lred[t >> 5] = s;
        __syncthreads();
        if (t == 0) {
            float tl = 0.f;
#pragma unroll
            for (int w = 0; w < 8; w++) tl += lred[w];
            out[0] = tl * (1.0f / (1024.0f * 1025.0f));
            g_done = 0;
        }
    }
}

extern "C" void kernel_launch(void* const* d_in, const int* in_sizes, int n_in,
                              void* d_out, int out_size) {
    const float* sentence;
    const int*   tgt;
    const float* W1;
    const float* b1;
    const float* W2;
    const float* b2;

    if (n_in >= 6 && in_sizes[1] == 1024) {
        sentence = (const float*)d_in[0];
        tgt      = (const int*)d_in[1];
        W1       = (const float*)d_in[2];
        b1       = (const float*)d_in[3];
        W2       = (const float*)d_in[4];
        b2       = (const float*)d_in[5];
    } else {
        sentence = (const float*)d_in[0];
        W1       = (const float*)d_in[1];
        b1       = (const float*)d_in[2];
        W2       = (const float*)d_in[3];
        b2       = (const float*)d_in[4];
        tgt      = (const int*)d_in[5];
    }

    float* out = (float*)d_out;

    dim3 g1(128, KSPLIT);
    k1_gemm<<<g1, 256>>>(sentence, W1);
    k1b_reduce<<<201, 256>>>(b1, W2, b2);
    dim3 g2(17, 32);
    k2_scores<<<g2, 256>>>(tgt);
    k3_softmax<<<NBLK3, 256>>>(out);
}